// round 12
// baseline (speedup 1.0000x reference)
#include <cuda_runtime.h>
#include <cuda_fp16.h>
#include <math.h>
#include <cstdint>

// ---------------- problem constants ----------------
#define Bn 2
#define Tn 4096
#define Dn 1024
#define Hn 16
#define KDn 512
#define VDn 1024
#define HKn 32
#define HVn 64
#define CHUNKn 64
#define NC (Tn / CHUNKn)          // 64 chunks
#define NTOK (Bn * Tn)            // 8192 tokens
#define BH (Bn * Hn)              // 32
#define NCB (NC * BH)             // 2048 chunk-heads
#define SCALE_Q 0.17677669529663687f  // 1/sqrt(32)

// ---------------- scratch (static device globals; no allocation) ----------------
__device__ float d_Q[NTOK * KDn];        // 16 MB
__device__ float d_Kb[NTOK * KDn];       // 16 MB
__device__ float d_Vb[NTOK * VDn];       // 32 MB
__device__ float d_Gb[NTOK * VDn];       // 32 MB
__device__ float d_GK[NTOK * KDn];       // 16 MB
__device__ float d_t16[NTOK * 16];       // 0.5 MB
__device__ float d_M[NCB * HKn * HVn];   // 16 MB
__device__ float d_Sb[NCB * HKn * HVn];  // 16 MB
__device__ float d_dl[NCB * HKn];        // 0.25 MB
__device__ float d_O[NTOK * VDn];        // 32 MB   intra-chunk o
__device__ __half d_Xh[NTOK * Dn];       // 16 MB   x in fp16
__device__ __half d_Oh[NTOK * VDn];      // 16 MB   gated o in fp16 (Wo input)
__device__ __half d_WqT[KDn * Dn];       // 1 MB    transposed fp16 weights (K-major)
__device__ __half d_WkT[KDn * Dn];       // 1 MB
__device__ __half d_WvT[VDn * Dn];       // 2 MB
__device__ __half d_WgT[VDn * Dn];       // 2 MB
__device__ __half d_WoT[Dn * Dn];        // 2 MB

// ---------------- helpers ----------------
__device__ __forceinline__ void mma_f16(float* c, const uint32_t* a, const uint32_t* b) {
    asm volatile(
        "mma.sync.aligned.m16n8k16.row.col.f32.f16.f16.f32 "
        "{%0,%1,%2,%3}, {%4,%5,%6,%7}, {%8,%9}, {%0,%1,%2,%3};"
        : "+f"(c[0]), "+f"(c[1]), "+f"(c[2]), "+f"(c[3])
        : "r"(a[0]), "r"(a[1]), "r"(a[2]), "r"(a[3]), "r"(b[0]), "r"(b[1]));
}
__device__ __forceinline__ void ldsm_x4(uint32_t* d, uint32_t addr) {
    asm volatile("ldmatrix.sync.aligned.m8n8.x4.shared.b16 {%0,%1,%2,%3}, [%4];"
        : "=r"(d[0]), "=r"(d[1]), "=r"(d[2]), "=r"(d[3]) : "r"(addr));
}
__device__ __forceinline__ void ldsm_x2(uint32_t* d, uint32_t addr) {
    asm volatile("ldmatrix.sync.aligned.m8n8.x2.shared.b16 {%0,%1}, [%2];"
        : "=r"(d[0]), "=r"(d[1]) : "r"(addr));
}

// ---------------- fp16 tensor-core GEMM: C[M,N] = A[M,K] * BT[N,K]^T ----------------
// Operands fp16 K-major, fp32 accumulate. Tile 128x128, K-step 64 (128B rows),
// 3-stage cp.async pipeline (96KB smem -> 2 CTAs/SM), SW128 xor swizzle,
// ldmatrix fragment loads, mma.sync m16n8k16.  (Round-7 proven version.)
#define GST 3
#define STAGE_BYTES 32768   // A 16KB + B 16KB
#define GEMM_DYNSMEM (GST * STAGE_BYTES)

__global__ __launch_bounds__(256, 2) void gemm_f16(
    const __half* __restrict__ A, const __half* __restrict__ BT,
    float* __restrict__ C, int M, int N, int K)
{
    extern __shared__ __align__(16) char dyn[];
    uint32_t sbase;
    asm("{ .reg .u64 t; cvta.to.shared.u64 t, %1; cvt.u32.u64 %0, t; }"
        : "=r"(sbase) : "l"(dyn));
    const int t = threadIdx.x;
    const int lane = t & 31;
    const int wrow = (t >> 5) >> 2;   // 0..1  (64 rows each)
    const int wcol = (t >> 5) & 3;    // 0..3  (32 cols each)
    const int bm = blockIdx.y << 7, bn = blockIdx.x << 7;
    const int NT = K >> 6;            // K tiles of 64 halves

    const int aoff = (wrow * 64 + ((lane >> 3) & 1) * 8 + (lane & 7)) * 128
                   + ((lane >> 4) & 1) * 16;              // + mt*2048 + ks*32
    const int boff = (wcol * 32 + (lane & 7)) * 128
                   + ((lane >> 3) & 1) * 16;              // + nt*1024 + ks*32

    #define LOAD_TILE(kt)                                                              \
    do {                                                                               \
        const int k0_ = (kt) << 6;                                                     \
        const uint32_t stg_ = sbase + ((kt) % GST) * STAGE_BYTES;                      \
        _Pragma("unroll")                                                              \
        for (int i_ = 0; i_ < 4; i_++) {                                               \
            int q_ = t + (i_ << 8);                                                    \
            int row_ = q_ >> 3, c16_ = q_ & 7;                                         \
            const __half* g_ = A + (size_t)(bm + row_) * K + k0_ + (c16_ << 3);        \
            uint32_t off_ = (uint32_t)((row_ << 7) + (c16_ << 4));                     \
            uint32_t dst_ = stg_ + (off_ ^ ((off_ >> 3) & 0x70));                      \
            asm volatile("cp.async.cg.shared.global [%0], [%1], 16;" :: "r"(dst_), "l"(g_)); \
        }                                                                              \
        _Pragma("unroll")                                                              \
        for (int i_ = 4; i_ < 8; i_++) {                                               \
            int q_ = t + (i_ << 8) - 1024;                                             \
            int row_ = q_ >> 3, c16_ = q_ & 7;                                         \
            const __half* g_ = BT + (size_t)(bn + row_) * K + k0_ + (c16_ << 3);       \
            uint32_t off_ = (uint32_t)((row_ << 7) + (c16_ << 4));                     \
            uint32_t dst_ = stg_ + 16384 + (off_ ^ ((off_ >> 3) & 0x70));              \
            asm volatile("cp.async.cg.shared.global [%0], [%1], 16;" :: "r"(dst_), "l"(g_)); \
        }                                                                              \
        asm volatile("cp.async.commit_group;");                                        \
    } while (0)

    float acc[4][4][4];
    #pragma unroll
    for (int i = 0; i < 4; i++)
        #pragma unroll
        for (int j = 0; j < 4; j++)
            #pragma unroll
            for (int e = 0; e < 4; e++) acc[i][j][e] = 0.f;

    LOAD_TILE(0);
    LOAD_TILE(1);

    for (int kt = 0; kt < NT; kt++) {
        asm volatile("cp.async.wait_group %0;" :: "n"(GST - 2));
        __syncthreads();
        const int nt_ = kt + GST - 1;
        if (nt_ < NT) LOAD_TILE(nt_);

        const uint32_t sAb = sbase + (kt % GST) * STAGE_BYTES;
        const uint32_t sBb = sAb + 16384;

        #pragma unroll
        for (int ks = 0; ks < 4; ks++) {
            uint32_t af[4][4], bf[4][2];
            #pragma unroll
            for (int mt = 0; mt < 4; mt++) {
                int o = aoff + mt * 2048 + ks * 32;
                ldsm_x4(af[mt], sAb + (o ^ ((o >> 3) & 0x70)));
            }
            #pragma unroll
            for (int nt = 0; nt < 4; nt++) {
                int o = boff + nt * 1024 + ks * 32;
                ldsm_x2(bf[nt], sBb + (o ^ ((o >> 3) & 0x70)));
            }
            #pragma unroll
            for (int mt = 0; mt < 4; mt++)
                #pragma unroll
                for (int nt = 0; nt < 4; nt++)
                    mma_f16(acc[mt][nt], af[mt], bf[nt]);
        }
    }

    #pragma unroll
    for (int mt = 0; mt < 4; mt++) {
        #pragma unroll
        for (int nt = 0; nt < 4; nt++) {
            int r0 = bm + wrow * 64 + mt * 16 + (lane >> 2);
            int c0 = bn + wcol * 32 + nt * 8 + (lane & 3) * 2;
            float2 v0 = make_float2(acc[mt][nt][0], acc[mt][nt][1]);
            float2 v1 = make_float2(acc[mt][nt][2], acc[mt][nt][3]);
            *(float2*)&C[(size_t)r0 * N + c0] = v0;
            *(float2*)&C[(size_t)(r0 + 8) * N + c0] = v1;
        }
    }
}

// ---------------- pre-passes ----------------
__global__ __launch_bounds__(256) void conv_x_kernel(const float* __restrict__ X,
                                                     __half* __restrict__ Y)
{
    int i = blockIdx.x * 256 + threadIdx.x;   // over float4s
    float4 v = ((const float4*)X)[i];
    __half2 lo = __floats2half2_rn(v.x, v.y);
    __half2 hi = __floats2half2_rn(v.z, v.w);
    ((uint2*)Y)[i] = make_uint2(*(uint32_t*)&lo, *(uint32_t*)&hi);
}

// merged transpose of all 5 weights (flat 32x32-tile grid)
struct TransPtrs {
    const float *wq, *wk, *wv, *wg, *wo;
    __half *qT, *kT, *vT, *gT, *oT;
};

__global__ __launch_bounds__(256) void transpose_all(TransPtrs p)
{
    __shared__ float tl[32][33];
    int bx = blockIdx.x;
    const float* W;
    __half* WT;
    int Kd, Nd, loc;
    if (bx < 512)       { W = p.wq; WT = p.qT; Kd = Dn;  Nd = KDn; loc = bx; }
    else if (bx < 1024) { W = p.wk; WT = p.kT; Kd = Dn;  Nd = KDn; loc = bx - 512; }
    else if (bx < 2048) { W = p.wv; WT = p.vT; Kd = Dn;  Nd = VDn; loc = bx - 1024; }
    else if (bx < 3072) { W = p.wg; WT = p.gT; Kd = Dn;  Nd = VDn; loc = bx - 2048; }
    else                { W = p.wo; WT = p.oT; Kd = VDn; Nd = Dn;  loc = bx - 3072; }
    const int nT = Nd >> 5;
    const int n0 = (loc % nT) * 32, k0 = (loc / nT) * 32;
    int tx = threadIdx.x & 31, ty = threadIdx.x >> 5;   // 32x8
    #pragma unroll
    for (int r = 0; r < 32; r += 8)
        tl[ty + r][tx] = W[(size_t)(k0 + ty + r) * Nd + n0 + tx];
    __syncthreads();
    #pragma unroll
    for (int r = 0; r < 32; r += 8)
        WT[(size_t)(n0 + ty + r) * Kd + k0 + tx] = __float2half_rn(tl[tx][ty + r]);
}

// ---------------- gk stage 1: t16 = x @ Wgk1 (fp32, smem-cached W) ----------
// 256 blocks x 32 rows; Wgk1 (64KB) staged once per block into smem.
// Warp per row; lanes: n = lane&15, k parity = lane>>4 (bank-conflict-free).
#define GK1_SMEM 65536
__global__ __launch_bounds__(256) void gemm_gk1(const float* __restrict__ X,
                                                const float* __restrict__ W)
{
    extern __shared__ float sW[];
    for (int i = threadIdx.x; i < Dn * 16; i += 256)
        sW[i] = W[i];
    __syncthreads();
    const int w = threadIdx.x >> 5, lane = threadIdx.x & 31;
    const int n = lane & 15, kh = lane >> 4;
    #pragma unroll
    for (int r = 0; r < 4; r++) {
        const int m = blockIdx.x * 32 + r * 8 + w;
        const float* xr = X + (size_t)m * Dn;
        float acc = 0.f;
        #pragma unroll 8
        for (int j = 0; j < Dn / 2; j++) {
            int k = 2 * j + kh;
            acc += xr[k] * sW[k * 16 + n];
        }
        acc += __shfl_xor_sync(0xffffffffu, acc, 16);
        if (kh == 0) d_t16[m * 16 + n] = acc;
    }
}

// ---------------- gk stage 2 ----------------
__global__ __launch_bounds__(256) void gk_kernel(const float* __restrict__ W2,
                                                 const float* __restrict__ bgk)
{
    int idx = blockIdx.x * blockDim.x + threadIdx.x;
    int m = idx >> 9;
    int n = idx & 511;
    const float* t = d_t16 + m * 16;
    float z = bgk[n];
    #pragma unroll
    for (int k = 0; k < 16; k++) z += t[k] * W2[k * KDn + n];
    float ls = fminf(z, 0.f) - log1pf(expf(-fabsf(z)));
    d_GK[idx] = ls * (1.f / 16.f);
}

// ---------------- attention phase A ----------------
__global__ __launch_bounds__(256) void attn_chunk_kernel()
{
    __shared__ float s_qe[2048];
    __shared__ float s_kd[2048];
    __shared__ float s_v[4096];
    __shared__ float s_A[2048];
    __shared__ float s_bl[32], s_dl[32];

    const int cb = blockIdx.x;
    const int bh = cb & 31, c = cb >> 5;
    const int b = bh >> 4, h = bh & 15;
    const int t = threadIdx.x;
    const size_t tok0 = (size_t)b * Tn + (size_t)c * CHUNKn;

    for (int e = t; e < 2048; e += 256) {
        int i = e >> 5, k = e & 31;
        s_qe[e] = d_GK[(tok0 + i) * KDn + h * HKn + k];
    }
    __syncthreads();
    if (t < 32) {
        float run = 0.f;
        for (int i = 0; i < 64; i++) { run += s_qe[i * 32 + t]; s_qe[i * 32 + t] = run; }
        s_bl[t] = run;
        s_dl[t] = expf(run);
    }
    __syncthreads();
    for (int e = t; e < 2048; e += 256) {
        int i = e >> 5, k = e & 31;
        float bb = s_qe[e];
        float kv = d_Kb[(tok0 + i) * KDn + h * HKn + k];
        s_kd[i * 32 + ((k ^ i) & 31)] = kv * expf(-bb);
        float qv = d_Q[(tok0 + i) * KDn + h * HKn + k];
        s_qe[e] = qv * expf(bb) * SCALE_Q;
    }
    for (int e = t; e < 4096; e += 256) {
        int i = e >> 6, v = e & 63;
        s_v[e] = d_Vb[(tok0 + i) * VDn + h * HVn + v];
    }
    __syncthreads();
    for (int o = t; o < 2048; o += 256) {
        int k = o >> 6, v = o & 63;
        float acc = 0.f;
        #pragma unroll 8
        for (int j = 0; j < 64; j++)
            acc += s_kd[j * 32 + ((k ^ j) & 31)] * s_v[j * 64 + v];
        d_M[(size_t)cb * 2048 + o] = acc * s_dl[k];
    }
    if (t < 32) d_dl[cb * 32 + t] = s_dl[t];

    #pragma unroll
    for (int half = 0; half < 2; half++) {
        __syncthreads();
        for (int o = t; o < 2048; o += 256) {
            int il = o >> 6, j = o & 63;
            int i = half * 32 + il;
            float acc = 0.f;
            if (j <= i) {
                #pragma unroll
                for (int k = 0; k < 32; k++)
                    acc += s_qe[i * 32 + k] * s_kd[j * 32 + ((k ^ j) & 31)];
            }
            s_A[o] = acc;
        }
        __syncthreads();
        for (int o = t; o < 2048; o += 256) {
            int il = o >> 6, v = o & 63;
            int i = half * 32 + il;
            float acc = 0.f;
            #pragma unroll 8
            for (int j = 0; j < 64; j++)
                acc += s_A[il * 64 + j] * s_v[j * 64 + v];
            d_O[(tok0 + i) * VDn + h * HVn + v] = acc;
        }
    }
}

// ---------------- attention phase B: serial state scan (128 blocks) -----------
__global__ __launch_bounds__(512) void scan_kernel()
{
    const int bh = blockIdx.x >> 2;                 // 0..31
    const int idx = (blockIdx.x & 3) * 512 + threadIdx.x;   // 0..2047
    float S = 0.f;
    for (int c = 0; c < NC; c++) {
        const int ch = c * 32 + bh;
        const size_t base = (size_t)ch * 2048;
        d_Sb[base + idx] = S;
        S = d_dl[ch * 32 + (idx >> 6)] * S + d_M[base + idx];
    }
}

// ---------------- attention phase C: inter-chunk + RMSNorm + SiLU gate ------------
// 16 threads per row (half-warp); RMS via shfl only — no syncthreads in the loop.
__global__ __launch_bounds__(256) void attn_inter_kernel(const float* __restrict__ norm_w)
{
    __shared__ float s_qe[2048];
    __shared__ float s_S[2048];

    const int cb = blockIdx.x;
    const int bh = cb & 31, c = cb >> 5;
    const int b = bh >> 4, h = bh & 15;
    const int t = threadIdx.x;
    const size_t tok0 = (size_t)b * Tn + (size_t)c * CHUNKn;

    for (int e = t; e < 2048; e += 256)
        s_qe[e] = d_GK[(tok0 + (e >> 5)) * KDn + h * HKn + (e & 31)];
    for (int e = t; e < 2048; e += 256)
        s_S[e] = d_Sb[(size_t)cb * 2048 + e];
    __syncthreads();
    if (t < 32) {
        float run = 0.f;
        for (int i = 0; i < 64; i++) { run += s_qe[i * 32 + t]; s_qe[i * 32 + t] = run; }
    }
    __syncthreads();
    for (int e = t; e < 2048; e += 256) {
        float bb = s_qe[e];
        float qv = d_Q[(tok0 + (e >> 5)) * KDn + h * HKn + (e & 31)];
        s_qe[e] = qv * expf(bb) * SCALE_Q;
    }
    __syncthreads();

    const float nw0 = norm_w[(t & 15) * 4 + 0];
    const float nw1 = norm_w[(t & 15) * 4 + 1];
    const float nw2 = norm_w[(t & 15) * 4 + 2];
    const float nw3 = norm_w[(t & 15) * 4 + 3];

    #pragma unroll
    for (int r = 0; r < 4; r++) {
        int i = r * 16 + (t >> 4);          // row 0..63
        int v4 = (t & 15) * 4;              // v-lane base
        size_t gi = (tok0 + i) * VDn + h * HVn + v4;
        float4 o4 = *(const float4*)&d_O[gi];
        float a0 = o4.x, a1 = o4.y, a2 = o4.z, a3 = o4.w;
        #pragma unroll
        for (int k = 0; k < 32; k++) {
            float q = s_qe[i * 32 + k];
            const float4 s4 = *(const float4*)&s_S[k * 64 + v4];
            a0 += q * s4.x; a1 += q * s4.y; a2 += q * s4.z; a3 += q * s4.w;
        }
        float ss = a0 * a0 + a1 * a1 + a2 * a2 + a3 * a3;
        ss += __shfl_xor_sync(0xffffffffu, ss, 8);
        ss += __shfl_xor_sync(0xffffffffu, ss, 4);
        ss += __shfl_xor_sync(0xffffffffu, ss, 2);
        ss += __shfl_xor_sync(0xffffffffu, ss, 1);
        float rinv = rsqrtf(ss * (1.f / 64.f) + 1e-5f);
        float4 g4 = *(const float4*)&d_Gb[gi];
        float sg0 = g4.x / (1.f + expf(-g4.x));
        float sg1 = g4.y / (1.f + expf(-g4.y));
        float sg2 = g4.z / (1.f + expf(-g4.z));
        float sg3 = g4.w / (1.f + expf(-g4.w));
        __half2 lo = __floats2half2_rn(a0 * rinv * nw0 * sg0, a1 * rinv * nw1 * sg1);
        __half2 hi = __floats2half2_rn(a2 * rinv * nw2 * sg2, a3 * rinv * nw3 * sg3);
        *(uint2*)&d_Oh[gi] = make_uint2(*(uint32_t*)&lo, *(uint32_t*)&hi);
    }
}

// ---------------- launch ----------------
extern "C" void kernel_launch(void* const* d_in, const int* in_sizes, int n_in,
                              void* d_out, int out_size)
{
    const float* x      = (const float*)d_in[0];
    const float* Wq     = (const float*)d_in[1];
    const float* Wk     = (const float*)d_in[2];
    const float* Wv     = (const float*)d_in[3];
    const float* Wgk1   = (const float*)d_in[4];
    const float* Wgk2   = (const float*)d_in[5];
    const float* bgk    = (const float*)d_in[6];
    const float* Wg     = (const float*)d_in[7];
    const float* norm_w = (const float*)d_in[8];
    const float* Wo     = (const float*)d_in[9];
    float* out = (float*)d_out;

    float *pQ, *pK, *pV, *pG;
    __half *pXh, *pOh, *pWqT, *pWkT, *pWvT, *pWgT, *pWoT;
    cudaGetSymbolAddress((void**)&pQ, d_Q);
    cudaGetSymbolAddress((void**)&pK, d_Kb);
    cudaGetSymbolAddress((void**)&pV, d_Vb);
    cudaGetSymbolAddress((void**)&pG, d_Gb);
    cudaGetSymbolAddress((void**)&pXh, d_Xh);
    cudaGetSymbolAddress((void**)&pOh, d_Oh);
    cudaGetSymbolAddress((void**)&pWqT, d_WqT);
    cudaGetSymbolAddress((void**)&pWkT, d_WkT);
    cudaGetSymbolAddress((void**)&pWvT, d_WvT);
    cudaGetSymbolAddress((void**)&pWgT, d_WgT);
    cudaGetSymbolAddress((void**)&pWoT, d_WoT);

    cudaFuncSetAttribute(gemm_f16, cudaFuncAttributeMaxDynamicSharedMemorySize,
                         GEMM_DYNSMEM);
    cudaFuncSetAttribute(gemm_gk1, cudaFuncAttributeMaxDynamicSharedMemorySize,
                         GK1_SMEM);

    // pre-passes: fp16 conversion + all weight transposes in one launch
    conv_x_kernel<<<(NTOK * Dn / 4) / 256, 256>>>(x, pXh);
    TransPtrs tp{Wq, Wk, Wv, Wg, Wo, pWqT, pWkT, pWvT, pWgT, pWoT};
    transpose_all<<<4096, 256>>>(tp);

    // projections on tensor cores (fp16 mma.sync m16n8k16 + ldmatrix)
    gemm_f16<<<dim3(KDn / 128, NTOK / 128), 256, GEMM_DYNSMEM>>>(pXh, pWqT, pQ, NTOK, KDn, Dn);
    gemm_f16<<<dim3(KDn / 128, NTOK / 128), 256, GEMM_DYNSMEM>>>(pXh, pWkT, pK, NTOK, KDn, Dn);
    gemm_f16<<<dim3(VDn / 128, NTOK / 128), 256, GEMM_DYNSMEM>>>(pXh, pWvT, pV, NTOK, VDn, Dn);
    gemm_f16<<<dim3(VDn / 128, NTOK / 128), 256, GEMM_DYNSMEM>>>(pXh, pWgT, pG, NTOK, VDn, Dn);

    // gate path (fp32 throughout)
    gemm_gk1<<<NTOK / 32, 256, GK1_SMEM>>>(x, Wgk1);
    gk_kernel<<<(NTOK * KDn) / 256, 256>>>(Wgk2, bgk);

    // chunked linear attention
    attn_chunk_kernel<<<NCB, 256>>>();
    scan_kernel<<<BH * 4, 512>>>();
    attn_inter_kernel<<<NCB, 256>>>(norm_w);

    // output projection
    gemm_f16<<<dim3(Dn / 128, NTOK / 128), 256, GEMM_DYNSMEM>>>(pOh, pWoT, out, NTOK, Dn, Dn);
}

// round 15
// speedup vs baseline: 1.1316x; 1.1316x over previous
#include <cuda_runtime.h>
#include <cuda_fp16.h>
#include <math.h>
#include <cstdint>

// ---------------- problem constants ----------------
#define Bn 2
#define Tn 4096
#define Dn 1024
#define Hn 16
#define KDn 512
#define VDn 1024
#define HKn 32
#define HVn 64
#define CHUNKn 64
#define NC (Tn / CHUNKn)          // 64 chunks
#define NTOK (Bn * Tn)            // 8192 tokens
#define BH (Bn * Hn)              // 32
#define NCB (NC * BH)             // 2048 chunk-heads
#define SCALE_Q 0.17677669529663687f  // 1/sqrt(32)

// ---------------- scratch (static device globals; no allocation) ----------------
__device__ float d_Q[NTOK * KDn];        // 16 MB
__device__ float d_Kb[NTOK * KDn];       // 16 MB
__device__ float d_Vb[NTOK * VDn];       // 32 MB
__device__ float d_Gb[NTOK * VDn];       // 32 MB
__device__ float d_GK[NTOK * KDn];       // 16 MB
__device__ float d_t16[NTOK * 16];       // 0.5 MB
__device__ float d_M[NCB * HKn * HVn];   // 16 MB
__device__ float d_Sb[NCB * HKn * HVn];  // 16 MB
__device__ float d_dl[NCB * HKn];        // 0.25 MB
__device__ float d_O[NTOK * VDn];        // 32 MB   intra-chunk o
__device__ __half d_Xh[NTOK * Dn];       // 16 MB   x in fp16
__device__ __half d_Oh[NTOK * VDn];      // 16 MB   gated o in fp16 (Wo input)
__device__ __half d_WqT[KDn * Dn];       // 1 MB    transposed fp16 weights (K-major)
__device__ __half d_WkT[KDn * Dn];       // 1 MB
__device__ __half d_WvT[VDn * Dn];       // 2 MB
__device__ __half d_WgT[VDn * Dn];       // 2 MB
__device__ __half d_WoT[Dn * Dn];        // 2 MB

// ---------------- helpers ----------------
__device__ __forceinline__ void mma_f16(float* c, const uint32_t* a, const uint32_t* b) {
    asm volatile(
        "mma.sync.aligned.m16n8k16.row.col.f32.f16.f16.f32 "
        "{%0,%1,%2,%3}, {%4,%5,%6,%7}, {%8,%9}, {%0,%1,%2,%3};"
        : "+f"(c[0]), "+f"(c[1]), "+f"(c[2]), "+f"(c[3])
        : "r"(a[0]), "r"(a[1]), "r"(a[2]), "r"(a[3]), "r"(b[0]), "r"(b[1]));
}
__device__ __forceinline__ void ldsm_x4(uint32_t* d, uint32_t addr) {
    asm volatile("ldmatrix.sync.aligned.m8n8.x4.shared.b16 {%0,%1,%2,%3}, [%4];"
        : "=r"(d[0]), "=r"(d[1]), "=r"(d[2]), "=r"(d[3]) : "r"(addr));
}
__device__ __forceinline__ void ldsm_x2(uint32_t* d, uint32_t addr) {
    asm volatile("ldmatrix.sync.aligned.m8n8.x2.shared.b16 {%0,%1}, [%2];"
        : "=r"(d[0]), "=r"(d[1]) : "r"(addr));
}

// ---------------- fp16 tensor-core GEMM (Round-7 proven) ----------------
#define GST 3
#define STAGE_BYTES 32768   // A 16KB + B 16KB
#define GEMM_DYNSMEM (GST * STAGE_BYTES)

__global__ __launch_bounds__(256, 2) void gemm_f16(
    const __half* __restrict__ A, const __half* __restrict__ BT,
    float* __restrict__ C, int M, int N, int K)
{
    extern __shared__ __align__(16) char dyn[];
    uint32_t sbase;
    asm("{ .reg .u64 t; cvta.to.shared.u64 t, %1; cvt.u32.u64 %0, t; }"
        : "=r"(sbase) : "l"(dyn));
    const int t = threadIdx.x;
    const int lane = t & 31;
    const int wrow = (t >> 5) >> 2;
    const int wcol = (t >> 5) & 3;
    const int bm = blockIdx.y << 7, bn = blockIdx.x << 7;
    const int NT = K >> 6;

    const int aoff = (wrow * 64 + ((lane >> 3) & 1) * 8 + (lane & 7)) * 128
                   + ((lane >> 4) & 1) * 16;
    const int boff = (wcol * 32 + (lane & 7)) * 128
                   + ((lane >> 3) & 1) * 16;

    #define LOAD_TILE(kt)                                                              \
    do {                                                                               \
        const int k0_ = (kt) << 6;                                                     \
        const uint32_t stg_ = sbase + ((kt) % GST) * STAGE_BYTES;                      \
        _Pragma("unroll")                                                              \
        for (int i_ = 0; i_ < 4; i_++) {                                               \
            int q_ = t + (i_ << 8);                                                    \
            int row_ = q_ >> 3, c16_ = q_ & 7;                                         \
            const __half* g_ = A + (size_t)(bm + row_) * K + k0_ + (c16_ << 3);        \
            uint32_t off_ = (uint32_t)((row_ << 7) + (c16_ << 4));                     \
            uint32_t dst_ = stg_ + (off_ ^ ((off_ >> 3) & 0x70));                      \
            asm volatile("cp.async.cg.shared.global [%0], [%1], 16;" :: "r"(dst_), "l"(g_)); \
        }                                                                              \
        _Pragma("unroll")                                                              \
        for (int i_ = 4; i_ < 8; i_++) {                                               \
            int q_ = t + (i_ << 8) - 1024;                                             \
            int row_ = q_ >> 3, c16_ = q_ & 7;                                         \
            const __half* g_ = BT + (size_t)(bn + row_) * K + k0_ + (c16_ << 3);       \
            uint32_t off_ = (uint32_t)((row_ << 7) + (c16_ << 4));                     \
            uint32_t dst_ = stg_ + 16384 + (off_ ^ ((off_ >> 3) & 0x70));              \
            asm volatile("cp.async.cg.shared.global [%0], [%1], 16;" :: "r"(dst_), "l"(g_)); \
        }                                                                              \
        asm volatile("cp.async.commit_group;");                                        \
    } while (0)

    float acc[4][4][4];
    #pragma unroll
    for (int i = 0; i < 4; i++)
        #pragma unroll
        for (int j = 0; j < 4; j++)
            #pragma unroll
            for (int e = 0; e < 4; e++) acc[i][j][e] = 0.f;

    LOAD_TILE(0);
    LOAD_TILE(1);

    for (int kt = 0; kt < NT; kt++) {
        asm volatile("cp.async.wait_group %0;" :: "n"(GST - 2));
        __syncthreads();
        const int nt_ = kt + GST - 1;
        if (nt_ < NT) LOAD_TILE(nt_);

        const uint32_t sAb = sbase + (kt % GST) * STAGE_BYTES;
        const uint32_t sBb = sAb + 16384;

        #pragma unroll
        for (int ks = 0; ks < 4; ks++) {
            uint32_t af[4][4], bf[4][2];
            #pragma unroll
            for (int mt = 0; mt < 4; mt++) {
                int o = aoff + mt * 2048 + ks * 32;
                ldsm_x4(af[mt], sAb + (o ^ ((o >> 3) & 0x70)));
            }
            #pragma unroll
            for (int nt = 0; nt < 4; nt++) {
                int o = boff + nt * 1024 + ks * 32;
                ldsm_x2(bf[nt], sBb + (o ^ ((o >> 3) & 0x70)));
            }
            #pragma unroll
            for (int mt = 0; mt < 4; mt++)
                #pragma unroll
                for (int nt = 0; nt < 4; nt++)
                    mma_f16(acc[mt][nt], af[mt], bf[nt]);
        }
    }

    #pragma unroll
    for (int mt = 0; mt < 4; mt++) {
        #pragma unroll
        for (int nt = 0; nt < 4; nt++) {
            int r0 = bm + wrow * 64 + mt * 16 + (lane >> 2);
            int c0 = bn + wcol * 32 + nt * 8 + (lane & 3) * 2;
            float2 v0 = make_float2(acc[mt][nt][0], acc[mt][nt][1]);
            float2 v1 = make_float2(acc[mt][nt][2], acc[mt][nt][3]);
            *(float2*)&C[(size_t)r0 * N + c0] = v0;
            *(float2*)&C[(size_t)(r0 + 8) * N + c0] = v1;
        }
    }
}

// ---------------- pre-passes ----------------
__global__ __launch_bounds__(256) void conv_x_kernel(const float* __restrict__ X,
                                                     __half* __restrict__ Y)
{
    int i = blockIdx.x * 256 + threadIdx.x;
    float4 v = ((const float4*)X)[i];
    __half2 lo = __floats2half2_rn(v.x, v.y);
    __half2 hi = __floats2half2_rn(v.z, v.w);
    ((uint2*)Y)[i] = make_uint2(*(uint32_t*)&lo, *(uint32_t*)&hi);
}

struct TransPtrs {
    const float *wq, *wk, *wv, *wg, *wo;
    __half *qT, *kT, *vT, *gT, *oT;
};

__global__ __launch_bounds__(256) void transpose_all(TransPtrs p)
{
    __shared__ float tl[32][33];
    int bx = blockIdx.x;
    const float* W;
    __half* WT;
    int Kd, Nd, loc;
    if (bx < 512)       { W = p.wq; WT = p.qT; Kd = Dn;  Nd = KDn; loc = bx; }
    else if (bx < 1024) { W = p.wk; WT = p.kT; Kd = Dn;  Nd = KDn; loc = bx - 512; }
    else if (bx < 2048) { W = p.wv; WT = p.vT; Kd = Dn;  Nd = VDn; loc = bx - 1024; }
    else if (bx < 3072) { W = p.wg; WT = p.gT; Kd = Dn;  Nd = VDn; loc = bx - 2048; }
    else                { W = p.wo; WT = p.oT; Kd = VDn; Nd = Dn;  loc = bx - 3072; }
    const int nT = Nd >> 5;
    const int n0 = (loc % nT) * 32, k0 = (loc / nT) * 32;
    int tx = threadIdx.x & 31, ty = threadIdx.x >> 5;
    #pragma unroll
    for (int r = 0; r < 32; r += 8)
        tl[ty + r][tx] = W[(size_t)(k0 + ty + r) * Nd + n0 + tx];
    __syncthreads();
    #pragma unroll
    for (int r = 0; r < 32; r += 8)
        WT[(size_t)(n0 + ty + r) * Kd + k0 + tx] = __float2half_rn(tl[tx][ty + r]);
}

// ---------------- gk stage 1: t16 = x @ Wgk1 ----------------
// 128 blocks x 64 rows. Wgk1 staged n-major in smem (conflict-free scalar LDS).
// Warp per row: lane-strided k (coalesced x LDG), 16 accumulators, shfl reduce.
#define GK1_SMEM 65536
__global__ __launch_bounds__(256) void gemm_gk1(const float* __restrict__ X,
                                                const float* __restrict__ W)
{
    extern __shared__ float sWt[];   // [16][1024] n-major
    for (int i = threadIdx.x; i < 16384; i += 256)
        sWt[(i & 15) * 1024 + (i >> 4)] = W[i];
    __syncthreads();
    const int w = threadIdx.x >> 5, lane = threadIdx.x & 31;
    for (int r = 0; r < 8; r++) {
        const int m = blockIdx.x * 64 + w * 8 + r;
        const float* xr = X + (size_t)m * Dn;
        float acc[16];
        #pragma unroll
        for (int n = 0; n < 16; n++) acc[n] = 0.f;
        #pragma unroll 4
        for (int j = 0; j < 32; j++) {
            float xv = xr[lane + 32 * j];
            #pragma unroll
            for (int n = 0; n < 16; n++)
                acc[n] += xv * sWt[n * 1024 + lane + 32 * j];
        }
        #pragma unroll
        for (int n = 0; n < 16; n++) {
            acc[n] += __shfl_xor_sync(0xffffffffu, acc[n], 16);
            acc[n] += __shfl_xor_sync(0xffffffffu, acc[n], 8);
            acc[n] += __shfl_xor_sync(0xffffffffu, acc[n], 4);
            acc[n] += __shfl_xor_sync(0xffffffffu, acc[n], 2);
            acc[n] += __shfl_xor_sync(0xffffffffu, acc[n], 1);
        }
        if (lane == 0) {
            #pragma unroll
            for (int n = 0; n < 16; n++)
                d_t16[m * 16 + n] = acc[n];
        }
    }
}

// ---------------- gk stage 2 ----------------
__global__ __launch_bounds__(256) void gk_kernel(const float* __restrict__ W2,
                                                 const float* __restrict__ bgk)
{
    int idx = blockIdx.x * blockDim.x + threadIdx.x;
    int m = idx >> 9;
    int n = idx & 511;
    const float* t = d_t16 + m * 16;
    float z = bgk[n];
    #pragma unroll
    for (int k = 0; k < 16; k++) z += t[k] * W2[k * KDn + n];
    float ls = fminf(z, 0.f) - log1pf(expf(-fabsf(z)));
    d_GK[idx] = ls * (1.f / 16.f);
}

// ---------------- attention phase A: register-tiled (LDS-traffic optimized) -------
// Per block: one chunk-head. s_A doubles as dl store (first 32) then full 64x64 A.
__global__ __launch_bounds__(256) void attn_chunk_kernel()
{
    __shared__ float s_qe[2048];   // g -> b -> qe (in-place), [i*32+k]
    __shared__ float s_kd[2048];   // k*exp(-b), XOR-swizzled [j*32 + ((k^j)&31)]
    __shared__ float s_v[4096];    // [j*64+v]
    __shared__ float s_A[4096];    // dl in [0..31] first, then A [i*64+j]

    const int cb = blockIdx.x;
    const int bh = cb & 31, c = cb >> 5;
    const int b = bh >> 4, h = bh & 15;
    const int t = threadIdx.x;
    const size_t tok0 = (size_t)b * Tn + (size_t)c * CHUNKn;

    for (int e = t; e < 2048; e += 256) {
        int i = e >> 5, k = e & 31;
        s_qe[e] = d_GK[(tok0 + i) * KDn + h * HKn + k];
    }
    __syncthreads();
    if (t < 32) {
        float run = 0.f;
        for (int i = 0; i < 64; i++) { run += s_qe[i * 32 + t]; s_qe[i * 32 + t] = run; }
        float dl = expf(run);
        s_A[t] = dl;
        d_dl[cb * 32 + t] = dl;
    }
    __syncthreads();
    for (int e = t; e < 2048; e += 256) {
        int i = e >> 5, k = e & 31;
        float bb = s_qe[e];
        s_kd[i * 32 + ((k ^ i) & 31)] = d_Kb[(tok0 + i) * KDn + h * HKn + k] * expf(-bb);
        s_qe[e] = d_Q[(tok0 + i) * KDn + h * HKn + k] * expf(bb) * SCALE_Q;
    }
    for (int e = t; e < 4096; e += 256)
        s_v[e] = d_Vb[(tok0 + (e >> 6)) * VDn + h * HVn + (e & 63)];
    __syncthreads();

    // ---- M[k][v] = dl[k] * sum_j kd[j][k] * v[j][v] ; thread: k in {kq,kq+16}, 4 v
    {
        const int kq = t >> 4;            // 0..15
        const int v4 = (t & 15) << 2;     // 0..60
        float4 m0 = make_float4(0.f, 0.f, 0.f, 0.f);
        float4 m1 = make_float4(0.f, 0.f, 0.f, 0.f);
        #pragma unroll 8
        for (int j = 0; j < 64; j++) {
            float kd0 = s_kd[j * 32 + ((kq ^ j) & 31)];
            float kd1 = s_kd[j * 32 + (((kq + 16) ^ j) & 31)];
            float4 vv = *(const float4*)&s_v[j * 64 + v4];
            m0.x += kd0 * vv.x; m0.y += kd0 * vv.y; m0.z += kd0 * vv.z; m0.w += kd0 * vv.w;
            m1.x += kd1 * vv.x; m1.y += kd1 * vv.y; m1.z += kd1 * vv.z; m1.w += kd1 * vv.w;
        }
        float dl0 = s_A[kq], dl1 = s_A[kq + 16];
        m0.x *= dl0; m0.y *= dl0; m0.z *= dl0; m0.w *= dl0;
        m1.x *= dl1; m1.y *= dl1; m1.z *= dl1; m1.w *= dl1;
        *(float4*)&d_M[(size_t)cb * 2048 + kq * 64 + v4] = m0;
        *(float4*)&d_M[(size_t)cb * 2048 + (kq + 16) * 64 + v4] = m1;
    }
    __syncthreads();   // dl reads done; s_A can be overwritten

    // ---- A[i][j] = sum_k qe[i][k] * kd[j][k], masked j<=i ; thread: 4i x 4j
    {
        const int i4 = (t >> 4) << 2;     // 0,4,...,60
        const int j4 = (t & 15) << 2;     // 0,4,...,60
        float aa[4][4];
        #pragma unroll
        for (int r = 0; r < 4; r++)
            #pragma unroll
            for (int cc = 0; cc < 4; cc++) aa[r][cc] = 0.f;
        #pragma unroll 8
        for (int k = 0; k < 32; k++) {
            float q0 = s_qe[(i4 + 0) * 32 + k];
            float q1 = s_qe[(i4 + 1) * 32 + k];
            float q2 = s_qe[(i4 + 2) * 32 + k];
            float q3 = s_qe[(i4 + 3) * 32 + k];
            float c0 = s_kd[(j4 + 0) * 32 + ((k ^ (j4 + 0)) & 31)];
            float c1 = s_kd[(j4 + 1) * 32 + ((k ^ (j4 + 1)) & 31)];
            float c2 = s_kd[(j4 + 2) * 32 + ((k ^ (j4 + 2)) & 31)];
            float c3 = s_kd[(j4 + 3) * 32 + ((k ^ (j4 + 3)) & 31)];
            aa[0][0] += q0 * c0; aa[0][1] += q0 * c1; aa[0][2] += q0 * c2; aa[0][3] += q0 * c3;
            aa[1][0] += q1 * c0; aa[1][1] += q1 * c1; aa[1][2] += q1 * c2; aa[1][3] += q1 * c3;
            aa[2][0] += q2 * c0; aa[2][1] += q2 * c1; aa[2][2] += q2 * c2; aa[2][3] += q2 * c3;
            aa[3][0] += q3 * c0; aa[3][1] += q3 * c1; aa[3][2] += q3 * c2; aa[3][3] += q3 * c3;
        }
        #pragma unroll
        for (int r = 0; r < 4; r++) {
            int i = i4 + r;
            float4 av;
            av.x = (j4 + 0 <= i) ? aa[r][0] : 0.f;
            av.y = (j4 + 1 <= i) ? aa[r][1] : 0.f;
            av.z = (j4 + 2 <= i) ? aa[r][2] : 0.f;
            av.w = (j4 + 3 <= i) ? aa[r][3] : 0.f;
            *(float4*)&s_A[i * 64 + j4] = av;
        }
    }
    __syncthreads();

    // ---- O_intra[i][v] = sum_j A[i][j] * v[j][v] ; thread: 4i x 4v, float4 loads
    {
        const int i4 = (t >> 4) << 2;
        const int v4 = (t & 15) << 2;
        float4 o0 = make_float4(0.f, 0.f, 0.f, 0.f);
        float4 o1 = o0, o2 = o0, o3 = o0;
        #pragma unroll 4
        for (int j0 = 0; j0 < 64; j0 += 4) {
            float4 vv0 = *(const float4*)&s_v[(j0 + 0) * 64 + v4];
            float4 vv1 = *(const float4*)&s_v[(j0 + 1) * 64 + v4];
            float4 vv2 = *(const float4*)&s_v[(j0 + 2) * 64 + v4];
            float4 vv3 = *(const float4*)&s_v[(j0 + 3) * 64 + v4];
            float4 a0 = *(const float4*)&s_A[(i4 + 0) * 64 + j0];
            float4 a1 = *(const float4*)&s_A[(i4 + 1) * 64 + j0];
            float4 a2 = *(const float4*)&s_A[(i4 + 2) * 64 + j0];
            float4 a3 = *(const float4*)&s_A[(i4 + 3) * 64 + j0];
            o0.x += a0.x * vv0.x + a0.y * vv1.x + a0.z * vv2.x + a0.w * vv3.x;
            o0.y += a0.x * vv0.y + a0.y * vv1.y + a0.z * vv2.y + a0.w * vv3.y;
            o0.z += a0.x * vv0.z + a0.y * vv1.z + a0.z * vv2.z + a0.w * vv3.z;
            o0.w += a0.x * vv0.w + a0.y * vv1.w + a0.z * vv2.w + a0.w * vv3.w;
            o1.x += a1.x * vv0.x + a1.y * vv1.x + a1.z * vv2.x + a1.w * vv3.x;
            o1.y += a1.x * vv0.y + a1.y * vv1.y + a1.z * vv2.y + a1.w * vv3.y;
            o1.z += a1.x * vv0.z + a1.y * vv1.z + a1.z * vv2.z + a1.w * vv3.z;
            o1.w += a1.x * vv0.w + a1.y * vv1.w + a1.z * vv2.w + a1.w * vv3.w;
            o2.x += a2.x * vv0.x + a2.y * vv1.x + a2.z * vv2.x + a2.w * vv3.x;
            o2.y += a2.x * vv0.y + a2.y * vv1.y + a2.z * vv2.y + a2.w * vv3.y;
            o2.z += a2.x * vv0.z + a2.y * vv1.z + a2.z * vv2.z + a2.w * vv3.z;
            o2.w += a2.x * vv0.w + a2.y * vv1.w + a2.z * vv2.w + a2.w * vv3.w;
            o3.x += a3.x * vv0.x + a3.y * vv1.x + a3.z * vv2.x + a3.w * vv3.x;
            o3.y += a3.x * vv0.y + a3.y * vv1.y + a3.z * vv2.y + a3.w * vv3.y;
            o3.z += a3.x * vv0.z + a3.y * vv1.z + a3.z * vv2.z + a3.w * vv3.z;
            o3.w += a3.x * vv0.w + a3.y * vv1.w + a3.z * vv2.w + a3.w * vv3.w;
        }
        *(float4*)&d_O[(tok0 + i4 + 0) * VDn + h * HVn + v4] = o0;
        *(float4*)&d_O[(tok0 + i4 + 1) * VDn + h * HVn + v4] = o1;
        *(float4*)&d_O[(tok0 + i4 + 2) * VDn + h * HVn + v4] = o2;
        *(float4*)&d_O[(tok0 + i4 + 3) * VDn + h * HVn + v4] = o3;
    }
}

// ---------------- attention phase B: serial state scan (128 blocks) -----------
__global__ __launch_bounds__(512) void scan_kernel()
{
    const int bh = blockIdx.x >> 2;
    const int idx = (blockIdx.x & 3) * 512 + threadIdx.x;
    float S = 0.f;
    for (int c = 0; c < NC; c++) {
        const int ch = c * 32 + bh;
        const size_t base = (size_t)ch * 2048;
        d_Sb[base + idx] = S;
        S = d_dl[ch * 32 + (idx >> 6)] * S + d_M[base + idx];
    }
}

// ---------------- attention phase C: inter-chunk + RMSNorm + SiLU gate ------------
__global__ __launch_bounds__(256) void attn_inter_kernel(const float* __restrict__ norm_w)
{
    __shared__ float s_qe[2048];
    __shared__ float s_S[2048];

    const int cb = blockIdx.x;
    const int bh = cb & 31, c = cb >> 5;
    const int b = bh >> 4, h = bh & 15;
    const int t = threadIdx.x;
    const size_t tok0 = (size_t)b * Tn + (size_t)c * CHUNKn;

    for (int e = t; e < 2048; e += 256)
        s_qe[e] = d_GK[(tok0 + (e >> 5)) * KDn + h * HKn + (e & 31)];
    for (int e = t; e < 2048; e += 256)
        s_S[e] = d_Sb[(size_t)cb * 2048 + e];
    __syncthreads();
    if (t < 32) {
        float run = 0.f;
        for (int i = 0; i < 64; i++) { run += s_qe[i * 32 + t]; s_qe[i * 32 + t] = run; }
    }
    __syncthreads();
    for (int e = t; e < 2048; e += 256) {
        float bb = s_qe[e];
        float qv = d_Q[(tok0 + (e >> 5)) * KDn + h * HKn + (e & 31)];
        s_qe[e] = qv * expf(bb) * SCALE_Q;
    }
    __syncthreads();

    const float nw0 = norm_w[(t & 15) * 4 + 0];
    const float nw1 = norm_w[(t & 15) * 4 + 1];
    const float nw2 = norm_w[(t & 15) * 4 + 2];
    const float nw3 = norm_w[(t & 15) * 4 + 3];

    #pragma unroll
    for (int r = 0; r < 4; r++) {
        int i = r * 16 + (t >> 4);
        int v4 = (t & 15) * 4;
        size_t gi = (tok0 + i) * VDn + h * HVn + v4;
        float4 o4 = *(const float4*)&d_O[gi];
        float a0 = o4.x, a1 = o4.y, a2 = o4.z, a3 = o4.w;
        #pragma unroll
        for (int k = 0; k < 32; k++) {
            float q = s_qe[i * 32 + k];
            const float4 s4 = *(const float4*)&s_S[k * 64 + v4];
            a0 += q * s4.x; a1 += q * s4.y; a2 += q * s4.z; a3 += q * s4.w;
        }
        float ss = a0 * a0 + a1 * a1 + a2 * a2 + a3 * a3;
        ss += __shfl_xor_sync(0xffffffffu, ss, 8);
        ss += __shfl_xor_sync(0xffffffffu, ss, 4);
        ss += __shfl_xor_sync(0xffffffffu, ss, 2);
        ss += __shfl_xor_sync(0xffffffffu, ss, 1);
        float rinv = rsqrtf(ss * (1.f / 64.f) + 1e-5f);
        float4 g4 = *(const float4*)&d_Gb[gi];
        float sg0 = g4.x / (1.f + expf(-g4.x));
        float sg1 = g4.y / (1.f + expf(-g4.y));
        float sg2 = g4.z / (1.f + expf(-g4.z));
        float sg3 = g4.w / (1.f + expf(-g4.w));
        __half2 lo = __floats2half2_rn(a0 * rinv * nw0 * sg0, a1 * rinv * nw1 * sg1);
        __half2 hi = __floats2half2_rn(a2 * rinv * nw2 * sg2, a3 * rinv * nw3 * sg3);
        *(uint2*)&d_Oh[gi] = make_uint2(*(uint32_t*)&lo, *(uint32_t*)&hi);
    }
}

// ---------------- launch ----------------
extern "C" void kernel_launch(void* const* d_in, const int* in_sizes, int n_in,
                              void* d_out, int out_size)
{
    const float* x      = (const float*)d_in[0];
    const float* Wq     = (const float*)d_in[1];
    const float* Wk     = (const float*)d_in[2];
    const float* Wv     = (const float*)d_in[3];
    const float* Wgk1   = (const float*)d_in[4];
    const float* Wgk2   = (const float*)d_in[5];
    const float* bgk    = (const float*)d_in[6];
    const float* Wg     = (const float*)d_in[7];
    const float* norm_w = (const float*)d_in[8];
    const float* Wo     = (const float*)d_in[9];
    float* out = (float*)d_out;

    float *pQ, *pK, *pV, *pG;
    __half *pXh, *pOh, *pWqT, *pWkT, *pWvT, *pWgT, *pWoT;
    cudaGetSymbolAddress((void**)&pQ, d_Q);
    cudaGetSymbolAddress((void**)&pK, d_Kb);
    cudaGetSymbolAddress((void**)&pV, d_Vb);
    cudaGetSymbolAddress((void**)&pG, d_Gb);
    cudaGetSymbolAddress((void**)&pXh, d_Xh);
    cudaGetSymbolAddress((void**)&pOh, d_Oh);
    cudaGetSymbolAddress((void**)&pWqT, d_WqT);
    cudaGetSymbolAddress((void**)&pWkT, d_WkT);
    cudaGetSymbolAddress((void**)&pWvT, d_WvT);
    cudaGetSymbolAddress((void**)&pWgT, d_WgT);
    cudaGetSymbolAddress((void**)&pWoT, d_WoT);

    cudaFuncSetAttribute(gemm_f16, cudaFuncAttributeMaxDynamicSharedMemorySize,
                         GEMM_DYNSMEM);
    cudaFuncSetAttribute(gemm_gk1, cudaFuncAttributeMaxDynamicSharedMemorySize,
                         GK1_SMEM);

    // pre-passes
    conv_x_kernel<<<(NTOK * Dn / 4) / 256, 256>>>(x, pXh);
    TransPtrs tp{Wq, Wk, Wv, Wg, Wo, pWqT, pWkT, pWvT, pWgT, pWoT};
    transpose_all<<<4096, 256>>>(tp);

    // projections on tensor cores
    gemm_f16<<<dim3(KDn / 128, NTOK / 128), 256, GEMM_DYNSMEM>>>(pXh, pWqT, pQ, NTOK, KDn, Dn);
    gemm_f16<<<dim3(KDn / 128, NTOK / 128), 256, GEMM_DYNSMEM>>>(pXh, pWkT, pK, NTOK, KDn, Dn);
    gemm_f16<<<dim3(VDn / 128, NTOK / 128), 256, GEMM_DYNSMEM>>>(pXh, pWvT, pV, NTOK, VDn, Dn);
    gemm_f16<<<dim3(VDn / 128, NTOK / 128), 256, GEMM_DYNSMEM>>>(pXh, pWgT, pG, NTOK, VDn, Dn);

    // gate path
    gemm_gk1<<<NTOK / 64, 256, GK1_SMEM>>>(x, Wgk1);
    gk_kernel<<<(NTOK * KDn) / 256, 256>>>(Wgk2, bgk);

    // chunked linear attention
    attn_chunk_kernel<<<NCB, 256>>>();
    scan_kernel<<<BH * 4, 512>>>();
    attn_inter_kernel<<<NCB, 256>>>(norm_w);

    // output projection
    gemm_f16<<<dim3(Dn / 128, NTOK / 128), 256, GEMM_DYNSMEM>>>(pOh, pWoT, out, NTOK, Dn, Dn);
}

// round 17
// speedup vs baseline: 1.2120x; 1.0711x over previous
#include <cuda_runtime.h>
#include <cuda_fp16.h>
#include <math.h>
#include <cstdint>

// ---------------- problem constants ----------------
#define Bn 2
#define Tn 4096
#define Dn 1024
#define Hn 16
#define KDn 512
#define VDn 1024
#define HKn 32
#define HVn 64
#define CHUNKn 64
#define NC (Tn / CHUNKn)          // 64 chunks
#define NTOK (Bn * Tn)            // 8192 tokens
#define BH (Bn * Hn)              // 32
#define NCB (NC * BH)             // 2048 chunk-heads
#define SCALE_Q 0.17677669529663687f  // 1/sqrt(32)

// ---------------- scratch (static device globals; no allocation) ----------------
__device__ float d_Q[NTOK * KDn];        // 16 MB
__device__ float d_Kb[NTOK * KDn];       // 16 MB
__device__ float d_Vb[NTOK * VDn];       // 32 MB
__device__ float d_Gb[NTOK * VDn];       // 32 MB
__device__ float d_t16[NTOK * 16];       // 0.5 MB
__device__ float d_M[NCB * HKn * HVn];   // 16 MB
__device__ float d_Sb[NCB * HKn * HVn];  // 16 MB
__device__ float d_dl[NCB * HKn];        // 0.25 MB
__device__ float d_O[NTOK * VDn];        // 32 MB   intra-chunk o
__device__ __half d_Xh[NTOK * Dn];       // 16 MB   x in fp16
__device__ __half d_Oh[NTOK * VDn];      // 16 MB   gated o in fp16 (Wo input)
__device__ __half d_WqT[KDn * Dn];       // 1 MB    transposed fp16 weights (K-major)
__device__ __half d_WkT[KDn * Dn];       // 1 MB
__device__ __half d_WvT[VDn * Dn];       // 2 MB
__device__ __half d_WgT[VDn * Dn];       // 2 MB
__device__ __half d_WoT[Dn * Dn];        // 2 MB

// ---------------- helpers ----------------
__device__ __forceinline__ void mma_f16(float* c, const uint32_t* a, const uint32_t* b) {
    asm volatile(
        "mma.sync.aligned.m16n8k16.row.col.f32.f16.f16.f32 "
        "{%0,%1,%2,%3}, {%4,%5,%6,%7}, {%8,%9}, {%0,%1,%2,%3};"
        : "+f"(c[0]), "+f"(c[1]), "+f"(c[2]), "+f"(c[3])
        : "r"(a[0]), "r"(a[1]), "r"(a[2]), "r"(a[3]), "r"(b[0]), "r"(b[1]));
}
__device__ __forceinline__ void ldsm_x4(uint32_t* d, uint32_t addr) {
    asm volatile("ldmatrix.sync.aligned.m8n8.x4.shared.b16 {%0,%1,%2,%3}, [%4];"
        : "=r"(d[0]), "=r"(d[1]), "=r"(d[2]), "=r"(d[3]) : "r"(addr));
}
__device__ __forceinline__ void ldsm_x2(uint32_t* d, uint32_t addr) {
    asm volatile("ldmatrix.sync.aligned.m8n8.x2.shared.b16 {%0,%1}, [%2];"
        : "=r"(d[0]), "=r"(d[1]) : "r"(addr));
}

// ---------------- fp16 tensor-core GEMM: C[M,N] = A[M,K] * BT[N,K]^T ----------------
// 128 threads, 4 warps in 2x2, warp tile 64x64 (halved LDS-crossbar traffic vs 64x32).
// Tile 128x128, K-step 64 halves, 3-stage cp.async (96KB smem -> 2 CTAs/SM), SW128.
#define GST 3
#define STAGE_BYTES 32768   // A 16KB + B 16KB
#define GEMM_DYNSMEM (GST * STAGE_BYTES)

__global__ __launch_bounds__(128, 2) void gemm_f16(
    const __half* __restrict__ A, const __half* __restrict__ BT,
    float* __restrict__ C, int M, int N, int K)
{
    extern __shared__ __align__(16) char dyn[];
    uint32_t sbase;
    asm("{ .reg .u64 t; cvta.to.shared.u64 t, %1; cvt.u32.u64 %0, t; }"
        : "=r"(sbase) : "l"(dyn));
    const int t = threadIdx.x;
    const int lane = t & 31;
    const int wrow = (t >> 5) >> 1;   // 0..1  (64 rows)
    const int wcol = (t >> 5) & 1;    // 0..1  (64 cols)
    const int bm = blockIdx.y << 7, bn = blockIdx.x << 7;
    const int NT = K >> 6;

    const int aoff = (wrow * 64 + ((lane >> 3) & 1) * 8 + (lane & 7)) * 128
                   + ((lane >> 4) & 1) * 16;              // + mt*2048 + ks*32
    const int boff = (wcol * 64 + (lane & 7)) * 128
                   + ((lane >> 3) & 1) * 16;              // + nt*1024 + ks*32

    #define LOAD_TILE(kt)                                                              \
    do {                                                                               \
        const int k0_ = (kt) << 6;                                                     \
        const uint32_t stg_ = sbase + ((kt) % GST) * STAGE_BYTES;                      \
        _Pragma("unroll")                                                              \
        for (int i_ = 0; i_ < 8; i_++) {                                               \
            int q_ = t + (i_ << 7);                                                    \
            int row_ = q_ >> 3, c16_ = q_ & 7;                                         \
            const __half* g_ = A + (size_t)(bm + row_) * K + k0_ + (c16_ << 3);        \
            uint32_t off_ = (uint32_t)((row_ << 7) + (c16_ << 4));                     \
            uint32_t dst_ = stg_ + (off_ ^ ((off_ >> 3) & 0x70));                      \
            asm volatile("cp.async.cg.shared.global [%0], [%1], 16;" :: "r"(dst_), "l"(g_)); \
        }                                                                              \
        _Pragma("unroll")                                                              \
        for (int i_ = 0; i_ < 8; i_++) {                                               \
            int q_ = t + (i_ << 7);                                                    \
            int row_ = q_ >> 3, c16_ = q_ & 7;                                         \
            const __half* g_ = BT + (size_t)(bn + row_) * K + k0_ + (c16_ << 3);       \
            uint32_t off_ = (uint32_t)((row_ << 7) + (c16_ << 4));                     \
            uint32_t dst_ = stg_ + 16384 + (off_ ^ ((off_ >> 3) & 0x70));              \
            asm volatile("cp.async.cg.shared.global [%0], [%1], 16;" :: "r"(dst_), "l"(g_)); \
        }                                                                              \
        asm volatile("cp.async.commit_group;");                                        \
    } while (0)

    float acc[4][8][4];
    #pragma unroll
    for (int i = 0; i < 4; i++)
        #pragma unroll
        for (int j = 0; j < 8; j++)
            #pragma unroll
            for (int e = 0; e < 4; e++) acc[i][j][e] = 0.f;

    LOAD_TILE(0);
    LOAD_TILE(1);

    for (int kt = 0; kt < NT; kt++) {
        asm volatile("cp.async.wait_group %0;" :: "n"(GST - 2));
        __syncthreads();
        const int nt_ = kt + GST - 1;
        if (nt_ < NT) LOAD_TILE(nt_);

        const uint32_t sAb = sbase + (kt % GST) * STAGE_BYTES;
        const uint32_t sBb = sAb + 16384;

        #pragma unroll
        for (int ks = 0; ks < 4; ks++) {
            uint32_t af[4][4], bf[8][2];
            #pragma unroll
            for (int mt = 0; mt < 4; mt++) {
                int o = aoff + mt * 2048 + ks * 32;
                ldsm_x4(af[mt], sAb + (o ^ ((o >> 3) & 0x70)));
            }
            #pragma unroll
            for (int nt = 0; nt < 8; nt++) {
                int o = boff + nt * 1024 + ks * 32;
                ldsm_x2(bf[nt], sBb + (o ^ ((o >> 3) & 0x70)));
            }
            #pragma unroll
            for (int mt = 0; mt < 4; mt++)
                #pragma unroll
                for (int nt = 0; nt < 8; nt++)
                    mma_f16(acc[mt][nt], af[mt], bf[nt]);
        }
    }

    #pragma unroll
    for (int mt = 0; mt < 4; mt++) {
        #pragma unroll
        for (int nt = 0; nt < 8; nt++) {
            int r0 = bm + wrow * 64 + mt * 16 + (lane >> 2);
            int c0 = bn + wcol * 64 + nt * 8 + (lane & 3) * 2;
            float2 v0 = make_float2(acc[mt][nt][0], acc[mt][nt][1]);
            float2 v1 = make_float2(acc[mt][nt][2], acc[mt][nt][3]);
            *(float2*)&C[(size_t)r0 * N + c0] = v0;
            *(float2*)&C[(size_t)(r0 + 8) * N + c0] = v1;
        }
    }
}

// ---------------- pre-passes ----------------
__global__ __launch_bounds__(256) void conv_x_kernel(const float* __restrict__ X,
                                                     __half* __restrict__ Y)
{
    int i = blockIdx.x * 256 + threadIdx.x;
    float4 v = ((const float4*)X)[i];
    __half2 lo = __floats2half2_rn(v.x, v.y);
    __half2 hi = __floats2half2_rn(v.z, v.w);
    ((uint2*)Y)[i] = make_uint2(*(uint32_t*)&lo, *(uint32_t*)&hi);
}

struct TransPtrs {
    const float *wq, *wk, *wv, *wg, *wo;
    __half *qT, *kT, *vT, *gT, *oT;
};

__global__ __launch_bounds__(256) void transpose_all(TransPtrs p)
{
    __shared__ float tl[32][33];
    int bx = blockIdx.x;
    const float* W;
    __half* WT;
    int Kd, Nd, loc;
    if (bx < 512)       { W = p.wq; WT = p.qT; Kd = Dn;  Nd = KDn; loc = bx; }
    else if (bx < 1024) { W = p.wk; WT = p.kT; Kd = Dn;  Nd = KDn; loc = bx - 512; }
    else if (bx < 2048) { W = p.wv; WT = p.vT; Kd = Dn;  Nd = VDn; loc = bx - 1024; }
    else if (bx < 3072) { W = p.wg; WT = p.gT; Kd = Dn;  Nd = VDn; loc = bx - 2048; }
    else                { W = p.wo; WT = p.oT; Kd = VDn; Nd = Dn;  loc = bx - 3072; }
    const int nT = Nd >> 5;
    const int n0 = (loc % nT) * 32, k0 = (loc / nT) * 32;
    int tx = threadIdx.x & 31, ty = threadIdx.x >> 5;
    #pragma unroll
    for (int r = 0; r < 32; r += 8)
        tl[ty + r][tx] = W[(size_t)(k0 + ty + r) * Nd + n0 + tx];
    __syncthreads();
    #pragma unroll
    for (int r = 0; r < 32; r += 8)
        WT[(size_t)(n0 + ty + r) * Kd + k0 + tx] = __float2half_rn(tl[tx][ty + r]);
}

// ---------------- gk stage 1: t16 = x @ Wgk1 ----------------
#define GK1_SMEM 65536
__global__ __launch_bounds__(256) void gemm_gk1(const float* __restrict__ X,
                                                const float* __restrict__ W)
{
    extern __shared__ float sWt[];   // [16][1024] n-major
    for (int i = threadIdx.x; i < 16384; i += 256)
        sWt[(i & 15) * 1024 + (i >> 4)] = W[i];
    __syncthreads();
    const int w = threadIdx.x >> 5, lane = threadIdx.x & 31;
    for (int r = 0; r < 8; r++) {
        const int m = blockIdx.x * 64 + w * 8 + r;
        const float* xr = X + (size_t)m * Dn;
        float acc[16];
        #pragma unroll
        for (int n = 0; n < 16; n++) acc[n] = 0.f;
        #pragma unroll 4
        for (int j = 0; j < 32; j++) {
            float xv = xr[lane + 32 * j];
            #pragma unroll
            for (int n = 0; n < 16; n++)
                acc[n] += xv * sWt[n * 1024 + lane + 32 * j];
        }
        #pragma unroll
        for (int n = 0; n < 16; n++) {
            acc[n] += __shfl_xor_sync(0xffffffffu, acc[n], 16);
            acc[n] += __shfl_xor_sync(0xffffffffu, acc[n], 8);
            acc[n] += __shfl_xor_sync(0xffffffffu, acc[n], 4);
            acc[n] += __shfl_xor_sync(0xffffffffu, acc[n], 2);
            acc[n] += __shfl_xor_sync(0xffffffffu, acc[n], 1);
        }
        if (lane == 0) {
            #pragma unroll
            for (int n = 0; n < 16; n++)
                d_t16[m * 16 + n] = acc[n];
        }
    }
}

// ---------------- attention phase A (fused GK; register-tiled) ----------------
// s_A reuse: [0..31] dl | [1024..2047] t16 tile | [2048..2559] Wgk2 slice, then full A.
__global__ __launch_bounds__(256) void attn_chunk_kernel(const float* __restrict__ W2,
                                                         const float* __restrict__ bgk)
{
    __shared__ float s_qe[2048];   // gk -> b -> qe (in-place), [i*32+k]
    __shared__ float s_kd[2048];   // k*exp(-b), XOR-swizzled [j*32 + ((k^j)&31)]
    __shared__ float s_v[4096];    // [j*64+v]
    __shared__ float s_A[4096];

    const int cb = blockIdx.x;
    const int bh = cb & 31, c = cb >> 5;
    const int b = bh >> 4, h = bh & 15;
    const int t = threadIdx.x;
    const size_t tok0 = (size_t)b * Tn + (size_t)c * CHUNKn;

    // stage t16 (64x16) and Wgk2 slice (16x32)
    for (int e = t; e < 1024; e += 256)
        s_A[1024 + e] = d_t16[(tok0 + (e >> 4)) * 16 + (e & 15)];
    for (int e = t; e < 512; e += 256)
        s_A[2048 + e] = W2[(e >> 5) * KDn + h * HKn + (e & 31)];
    __syncthreads();

    // GK = log_sigmoid(t16 @ W2 + bgk) / 16   (bit-identical to old gk_kernel)
    for (int e = t; e < 2048; e += 256) {
        int i = e >> 5, k = e & 31;
        float z = bgk[h * HKn + k];
        #pragma unroll
        for (int j = 0; j < 16; j++)
            z += s_A[1024 + i * 16 + j] * s_A[2048 + j * 32 + k];
        s_qe[e] = (fminf(z, 0.f) - log1pf(expf(-fabsf(z)))) * (1.f / 16.f);
    }
    __syncthreads();

    if (t < 32) {
        float run = 0.f;
        for (int i = 0; i < 64; i++) { run += s_qe[i * 32 + t]; s_qe[i * 32 + t] = run; }
        float dl = expf(run);
        s_A[t] = dl;
        d_dl[cb * 32 + t] = dl;
    }
    __syncthreads();
    for (int e = t; e < 2048; e += 256) {
        int i = e >> 5, k = e & 31;
        float bb = s_qe[e];
        s_kd[i * 32 + ((k ^ i) & 31)] = d_Kb[(tok0 + i) * KDn + h * HKn + k] * expf(-bb);
        s_qe[e] = d_Q[(tok0 + i) * KDn + h * HKn + k] * expf(bb) * SCALE_Q;
    }
    for (int e = t; e < 4096; e += 256)
        s_v[e] = d_Vb[(tok0 + (e >> 6)) * VDn + h * HVn + (e & 63)];
    __syncthreads();

    // ---- M[k][v] = dl[k] * sum_j kd[j][k] * v[j][v]
    {
        const int kq = t >> 4;
        const int v4 = (t & 15) << 2;
        float4 m0 = make_float4(0.f, 0.f, 0.f, 0.f);
        float4 m1 = make_float4(0.f, 0.f, 0.f, 0.f);
        #pragma unroll 8
        for (int j = 0; j < 64; j++) {
            float kd0 = s_kd[j * 32 + ((kq ^ j) & 31)];
            float kd1 = s_kd[j * 32 + (((kq + 16) ^ j) & 31)];
            float4 vv = *(const float4*)&s_v[j * 64 + v4];
            m0.x += kd0 * vv.x; m0.y += kd0 * vv.y; m0.z += kd0 * vv.z; m0.w += kd0 * vv.w;
            m1.x += kd1 * vv.x; m1.y += kd1 * vv.y; m1.z += kd1 * vv.z; m1.w += kd1 * vv.w;
        }
        float dl0 = s_A[kq], dl1 = s_A[kq + 16];
        m0.x *= dl0; m0.y *= dl0; m0.z *= dl0; m0.w *= dl0;
        m1.x *= dl1; m1.y *= dl1; m1.z *= dl1; m1.w *= dl1;
        *(float4*)&d_M[(size_t)cb * 2048 + kq * 64 + v4] = m0;
        *(float4*)&d_M[(size_t)cb * 2048 + (kq + 16) * 64 + v4] = m1;
    }
    __syncthreads();

    // ---- A[i][j] = sum_k qe[i][k] * kd[j][k], masked j<=i
    {
        const int i4 = (t >> 4) << 2;
        const int j4 = (t & 15) << 2;
        float aa[4][4];
        #pragma unroll
        for (int r = 0; r < 4; r++)
            #pragma unroll
            for (int cc = 0; cc < 4; cc++) aa[r][cc] = 0.f;
        #pragma unroll 8
        for (int k = 0; k < 32; k++) {
            float q0 = s_qe[(i4 + 0) * 32 + k];
            float q1 = s_qe[(i4 + 1) * 32 + k];
            float q2 = s_qe[(i4 + 2) * 32 + k];
            float q3 = s_qe[(i4 + 3) * 32 + k];
            float c0 = s_kd[(j4 + 0) * 32 + ((k ^ (j4 + 0)) & 31)];
            float c1 = s_kd[(j4 + 1) * 32 + ((k ^ (j4 + 1)) & 31)];
            float c2 = s_kd[(j4 + 2) * 32 + ((k ^ (j4 + 2)) & 31)];
            float c3 = s_kd[(j4 + 3) * 32 + ((k ^ (j4 + 3)) & 31)];
            aa[0][0] += q0 * c0; aa[0][1] += q0 * c1; aa[0][2] += q0 * c2; aa[0][3] += q0 * c3;
            aa[1][0] += q1 * c0; aa[1][1] += q1 * c1; aa[1][2] += q1 * c2; aa[1][3] += q1 * c3;
            aa[2][0] += q2 * c0; aa[2][1] += q2 * c1; aa[2][2] += q2 * c2; aa[2][3] += q2 * c3;
            aa[3][0] += q3 * c0; aa[3][1] += q3 * c1; aa[3][2] += q3 * c2; aa[3][3] += q3 * c3;
        }
        #pragma unroll
        for (int r = 0; r < 4; r++) {
            int i = i4 + r;
            float4 av;
            av.x = (j4 + 0 <= i) ? aa[r][0] : 0.f;
            av.y = (j4 + 1 <= i) ? aa[r][1] : 0.f;
            av.z = (j4 + 2 <= i) ? aa[r][2] : 0.f;
            av.w = (j4 + 3 <= i) ? aa[r][3] : 0.f;
            *(float4*)&s_A[i * 64 + j4] = av;
        }
    }
    __syncthreads();

    // ---- O_intra[i][v] = sum_j A[i][j] * v[j][v]
    {
        const int i4 = (t >> 4) << 2;
        const int v4 = (t & 15) << 2;
        float4 o0 = make_float4(0.f, 0.f, 0.f, 0.f);
        float4 o1 = o0, o2 = o0, o3 = o0;
        #pragma unroll 4
        for (int j0 = 0; j0 < 64; j0 += 4) {
            float4 vv0 = *(const float4*)&s_v[(j0 + 0) * 64 + v4];
            float4 vv1 = *(const float4*)&s_v[(j0 + 1) * 64 + v4];
            float4 vv2 = *(const float4*)&s_v[(j0 + 2) * 64 + v4];
            float4 vv3 = *(const float4*)&s_v[(j0 + 3) * 64 + v4];
            float4 a0 = *(const float4*)&s_A[(i4 + 0) * 64 + j0];
            float4 a1 = *(const float4*)&s_A[(i4 + 1) * 64 + j0];
            float4 a2 = *(const float4*)&s_A[(i4 + 2) * 64 + j0];
            float4 a3 = *(const float4*)&s_A[(i4 + 3) * 64 + j0];
            o0.x += a0.x * vv0.x + a0.y * vv1.x + a0.z * vv2.x + a0.w * vv3.x;
            o0.y += a0.x * vv0.y + a0.y * vv1.y + a0.z * vv2.y + a0.w * vv3.y;
            o0.z += a0.x * vv0.z + a0.y * vv1.z + a0.z * vv2.z + a0.w * vv3.z;
            o0.w += a0.x * vv0.w + a0.y * vv1.w + a0.z * vv2.w + a0.w * vv3.w;
            o1.x += a1.x * vv0.x + a1.y * vv1.x + a1.z * vv2.x + a1.w * vv3.x;
            o1.y += a1.x * vv0.y + a1.y * vv1.y + a1.z * vv2.y + a1.w * vv3.y;
            o1.z += a1.x * vv0.z + a1.y * vv1.z + a1.z * vv2.z + a1.w * vv3.z;
            o1.w += a1.x * vv0.w + a1.y * vv1.w + a1.z * vv2.w + a1.w * vv3.w;
            o2.x += a2.x * vv0.x + a2.y * vv1.x + a2.z * vv2.x + a2.w * vv3.x;
            o2.y += a2.x * vv0.y + a2.y * vv1.y + a2.z * vv2.y + a2.w * vv3.y;
            o2.z += a2.x * vv0.z + a2.y * vv1.z + a2.z * vv2.z + a2.w * vv3.z;
            o2.w += a2.x * vv0.w + a2.y * vv1.w + a2.z * vv2.w + a2.w * vv3.w;
            o3.x += a3.x * vv0.x + a3.y * vv1.x + a3.z * vv2.x + a3.w * vv3.x;
            o3.y += a3.x * vv0.y + a3.y * vv1.y + a3.z * vv2.y + a3.w * vv3.y;
            o3.z += a3.x * vv0.z + a3.y * vv1.z + a3.z * vv2.z + a3.w * vv3.z;
            o3.w += a3.x * vv0.w + a3.y * vv1.w + a3.z * vv2.w + a3.w * vv3.w;
        }
        *(float4*)&d_O[(tok0 + i4 + 0) * VDn + h * HVn + v4] = o0;
        *(float4*)&d_O[(tok0 + i4 + 1) * VDn + h * HVn + v4] = o1;
        *(float4*)&d_O[(tok0 + i4 + 2) * VDn + h * HVn + v4] = o2;
        *(float4*)&d_O[(tok0 + i4 + 3) * VDn + h * HVn + v4] = o3;
    }
}

// ---------------- attention phase B: serial state scan (128 blocks) -----------
__global__ __launch_bounds__(512) void scan_kernel()
{
    const int bh = blockIdx.x >> 2;
    const int idx = (blockIdx.x & 3) * 512 + threadIdx.x;
    float S = 0.f;
    for (int c = 0; c < NC; c++) {
        const int ch = c * 32 + bh;
        const size_t base = (size_t)ch * 2048;
        d_Sb[base + idx] = S;
        S = d_dl[ch * 32 + (idx >> 6)] * S + d_M[base + idx];
    }
}

// ---------------- attention phase C: inter-chunk + RMSNorm + SiLU (fused GK) ------
__global__ __launch_bounds__(256) void attn_inter_kernel(const float* __restrict__ norm_w,
                                                         const float* __restrict__ W2,
                                                         const float* __restrict__ bgk)
{
    __shared__ float s_qe[2048];
    __shared__ float s_S[2048];
    __shared__ float s_t16[1024];
    __shared__ float s_w2[512];

    const int cb = blockIdx.x;
    const int bh = cb & 31, c = cb >> 5;
    const int b = bh >> 4, h = bh & 15;
    const int t = threadIdx.x;
    const size_t tok0 = (size_t)b * Tn + (size_t)c * CHUNKn;

    for (int e = t; e < 1024; e += 256)
        s_t16[e] = d_t16[(tok0 + (e >> 4)) * 16 + (e & 15)];
    for (int e = t; e < 512; e += 256)
        s_w2[e] = W2[(e >> 5) * KDn + h * HKn + (e & 31)];
    for (int e = t; e < 2048; e += 256)
        s_S[e] = d_Sb[(size_t)cb * 2048 + e];
    __syncthreads();

    for (int e = t; e < 2048; e += 256) {
        int i = e >> 5, k = e & 31;
        float z = bgk[h * HKn + k];
        #pragma unroll
        for (int j = 0; j < 16; j++)
            z += s_t16[i * 16 + j] * s_w2[j * 32 + k];
        s_qe[e] = (fminf(z, 0.f) - log1pf(expf(-fabsf(z)))) * (1.f / 16.f);
    }
    __syncthreads();
    if (t < 32) {
        float run = 0.f;
        for (int i = 0; i < 64; i++) { run += s_qe[i * 32 + t]; s_qe[i * 32 + t] = run; }
    }
    __syncthreads();
    for (int e = t; e < 2048; e += 256) {
        float bb = s_qe[e];
        float qv = d_Q[(tok0 + (e >> 5)) * KDn + h * HKn + (e & 31)];
        s_qe[e] = qv * expf(bb) * SCALE_Q;
    }
    __syncthreads();

    const float nw0 = norm_w[(t & 15) * 4 + 0];
    const float nw1 = norm_w[(t & 15) * 4 + 1];
    const float nw2 = norm_w[(t & 15) * 4 + 2];
    const float nw3 = norm_w[(t & 15) * 4 + 3];

    #pragma unroll
    for (int r = 0; r < 4; r++) {
        int i = r * 16 + (t >> 4);
        int v4 = (t & 15) * 4;
        size_t gi = (tok0 + i) * VDn + h * HVn + v4;
        float4 o4 = *(const float4*)&d_O[gi];
        float a0 = o4.x, a1 = o4.y, a2 = o4.z, a3 = o4.w;
        #pragma unroll
        for (int k = 0; k < 32; k++) {
            float q = s_qe[i * 32 + k];
            const float4 s4 = *(const float4*)&s_S[k * 64 + v4];
            a0 += q * s4.x; a1 += q * s4.y; a2 += q * s4.z; a3 += q * s4.w;
        }
        float ss = a0 * a0 + a1 * a1 + a2 * a2 + a3 * a3;
        ss += __shfl_xor_sync(0xffffffffu, ss, 8);
        ss += __shfl_xor_sync(0xffffffffu, ss, 4);
        ss += __shfl_xor_sync(0xffffffffu, ss, 2);
        ss += __shfl_xor_sync(0xffffffffu, ss, 1);
        float rinv = rsqrtf(ss * (1.f / 64.f) + 1e-5f);
        float4 g4 = *(const float4*)&d_Gb[gi];
        float sg0 = g4.x / (1.f + expf(-g4.x));
        float sg1 = g4.y / (1.f + expf(-g4.y));
        float sg2 = g4.z / (1.f + expf(-g4.z));
        float sg3 = g4.w / (1.f + expf(-g4.w));
        __half2 lo = __floats2half2_rn(a0 * rinv * nw0 * sg0, a1 * rinv * nw1 * sg1);
        __half2 hi = __floats2half2_rn(a2 * rinv * nw2 * sg2, a3 * rinv * nw3 * sg3);
        *(uint2*)&d_Oh[gi] = make_uint2(*(uint32_t*)&lo, *(uint32_t*)&hi);
    }
}

// ---------------- launch ----------------
extern "C" void kernel_launch(void* const* d_in, const int* in_sizes, int n_in,
                              void* d_out, int out_size)
{
    const float* x      = (const float*)d_in[0];
    const float* Wq     = (const float*)d_in[1];
    const float* Wk     = (const float*)d_in[2];
    const float* Wv     = (const float*)d_in[3];
    const float* Wgk1   = (const float*)d_in[4];
    const float* Wgk2   = (const float*)d_in[5];
    const float* bgk    = (const float*)d_in[6];
    const float* Wg     = (const float*)d_in[7];
    const float* norm_w = (const float*)d_in[8];
    const float* Wo     = (const float*)d_in[9];
    float* out = (float*)d_out;

    float *pQ, *pK, *pV, *pG;
    __half *pXh, *pOh, *pWqT, *pWkT, *pWvT, *pWgT, *pWoT;
    cudaGetSymbolAddress((void**)&pQ, d_Q);
    cudaGetSymbolAddress((void**)&pK, d_Kb);
    cudaGetSymbolAddress((void**)&pV, d_Vb);
    cudaGetSymbolAddress((void**)&pG, d_Gb);
    cudaGetSymbolAddress((void**)&pXh, d_Xh);
    cudaGetSymbolAddress((void**)&pOh, d_Oh);
    cudaGetSymbolAddress((void**)&pWqT, d_WqT);
    cudaGetSymbolAddress((void**)&pWkT, d_WkT);
    cudaGetSymbolAddress((void**)&pWvT, d_WvT);
    cudaGetSymbolAddress((void**)&pWgT, d_WgT);
    cudaGetSymbolAddress((void**)&pWoT, d_WoT);

    cudaFuncSetAttribute(gemm_f16, cudaFuncAttributeMaxDynamicSharedMemorySize,
                         GEMM_DYNSMEM);
    cudaFuncSetAttribute(gemm_gk1, cudaFuncAttributeMaxDynamicSharedMemorySize,
                         GK1_SMEM);

    // pre-passes
    conv_x_kernel<<<(NTOK * Dn / 4) / 256, 256>>>(x, pXh);
    TransPtrs tp{Wq, Wk, Wv, Wg, Wo, pWqT, pWkT, pWvT, pWgT, pWoT};
    transpose_all<<<4096, 256>>>(tp);

    // projections on tensor cores (128-thread, 64x64 warp-tile GEMM)
    gemm_f16<<<dim3(KDn / 128, NTOK / 128), 128, GEMM_DYNSMEM>>>(pXh, pWqT, pQ, NTOK, KDn, Dn);
    gemm_f16<<<dim3(KDn / 128, NTOK / 128), 128, GEMM_DYNSMEM>>>(pXh, pWkT, pK, NTOK, KDn, Dn);
    gemm_f16<<<dim3(VDn / 128, NTOK / 128), 128, GEMM_DYNSMEM>>>(pXh, pWvT, pV, NTOK, VDn, Dn);
    gemm_f16<<<dim3(VDn / 128, NTOK / 128), 128, GEMM_DYNSMEM>>>(pXh, pWgT, pG, NTOK, VDn, Dn);

    // gate path stage 1 (stage 2 fused into attention kernels)
    gemm_gk1<<<NTOK / 64, 256, GK1_SMEM>>>(x, Wgk1);

    // chunked linear attention
    attn_chunk_kernel<<<NCB, 256>>>(Wgk2, bgk);
    scan_kernel<<<BH * 4, 512>>>();
    attn_inter_kernel<<<NCB, 256>>>(norm_w, Wgk2, bgk);

    // output projection
    gemm_f16<<<dim3(Dn / 128, NTOK / 128), 128, GEMM_DYNSMEM>>>(pOh, pWoT, out, NTOK, Dn, Dn);
}